// round 15
// baseline (speedup 1.0000x reference)
#include <cuda_runtime.h>
#include <cuda_fp16.h>
#include <cstdint>
#include <cstddef>

// ---------------------------------------------------------------------------
// Problem constants
// ---------------------------------------------------------------------------
#define HIDDEN   768
#define META     25
#define ED_COUNT 300
#define BATCH    2
#define N_MENT   2000
#define N_PAIRS  40000
#define M_TOTAL  (BATCH * N_MENT)        // 4000
#define N_TOTAL  (2 * HIDDEN)            // 1536
#define P_TOTAL  (BATCH * N_PAIRS)       // 80000

// ---------------------------------------------------------------------------
// Device scratch
// ---------------------------------------------------------------------------
__device__ __half g_ACh[(size_t)M_TOTAL * N_TOTAL];   // 12.3 MB  (A|C rows, fp16)
__device__ __half g_Eh[(size_t)ED_COUNT * HIDDEN];    // 0.46 MB
__device__ __half g_Ah[(size_t)M_TOTAL * HIDDEN];     // 6.1 MB  mentions fp16
__device__ __half g_Bh[(size_t)N_TOTAL * HIDDEN];     // 2.4 MB  W1^T fp16 [n][k]
__device__ int  g_hist[M_TOTAL];                      // bucket counts -> cursors
__device__ int4 g_sorted[P_TOTAL];                    // {i1g, i2g, ed, p}

// ---------------------------------------------------------------------------
// helpers
// ---------------------------------------------------------------------------
__device__ __forceinline__ uint32_t smem_u32(const void* p) {
    uint32_t a;
    asm("{ .reg .u64 t; cvta.to.shared.u64 t, %1; cvt.u32.u64 %0, t; }" : "=r"(a) : "l"(p));
    return a;
}
__device__ __forceinline__ void cp_async16(uint32_t dst, const void* src, uint32_t src_bytes) {
    asm volatile("cp.async.ca.shared.global [%0], [%1], 16, %2;"
                 :: "r"(dst), "l"(src), "r"(src_bytes) : "memory");
}
__device__ __forceinline__ void ldsm_x4(uint32_t& r0, uint32_t& r1, uint32_t& r2,
                                        uint32_t& r3, uint32_t addr) {
    asm volatile("ldmatrix.sync.aligned.m8n8.x4.shared.b16 {%0,%1,%2,%3}, [%4];"
                 : "=r"(r0), "=r"(r1), "=r"(r2), "=r"(r3) : "r"(addr));
}
__device__ __forceinline__ void mma_f16(float* c, const uint32_t* a, const uint32_t* b) {
    asm volatile(
        "mma.sync.aligned.m16n8k16.row.col.f32.f16.f16.f32 "
        "{%0,%1,%2,%3}, {%4,%5,%6,%7}, {%8,%9}, {%0,%1,%2,%3};"
        : "+f"(c[0]), "+f"(c[1]), "+f"(c[2]), "+f"(c[3])
        : "r"(a[0]), "r"(a[1]), "r"(a[2]), "r"(a[3]), "r"(b[0]), "r"(b[1]));
}
__device__ __forceinline__ float2 h2f(uint32_t u) {
    __half2 h = *reinterpret_cast<__half2*>(&u);
    return __half22float2(h);
}

// ---------------------------------------------------------------------------
// Prep: fp32 -> fp16; also zeroes the sort histogram (fused, saves a launch)
// ---------------------------------------------------------------------------
__global__ __launch_bounds__(256)
void prep_a(const float* __restrict__ A)
{
    int i = blockIdx.x * 256 + threadIdx.x;          // one float4 per thread
    if (i < M_TOTAL) g_hist[i] = 0;
    if (i * 4 >= M_TOTAL * HIDDEN) return;
    float4 v = ((const float4*)A)[i];
    __half2* dst = (__half2*)(g_Ah + (size_t)i * 4);
    dst[0] = __floats2half2_rn(v.x, v.y);
    dst[1] = __floats2half2_rn(v.z, v.w);
}

__global__ void prep_b(const float* __restrict__ W1)
{
    __shared__ float t[32][33];
    const int kt = blockIdx.x;              // 0..23 (k tile within half)
    const int nt = blockIdx.y;              // 0..47 (global n tile)
    const int half = (nt * 32) >= HIDDEN;
    const int nloc = nt * 32 - half * HIDDEN;
    const int c = threadIdx.x;
    for (int r = threadIdx.y; r < 32; r += 8)
        t[r][c] = W1[(size_t)(half * HIDDEN + kt * 32 + r) * HIDDEN + nloc + c];
    __syncthreads();
    for (int rr = threadIdx.y; rr < 32; rr += 8) {
        float v = t[c][rr];
        g_Bh[(size_t)(nt * 32 + rr) * HIDDEN + kt * 32 + c] = __float2half_rn(v);
    }
}

// ---------------------------------------------------------------------------
// Counting sort of pairs by (batch, i1): count -> scan -> scatter
// ---------------------------------------------------------------------------
__global__ __launch_bounds__(256)
void sort_count(const int* __restrict__ pairs)
{
    int p = blockIdx.x * 256 + threadIdx.x;
    if (p >= P_TOTAL) return;
    int key = (p / N_PAIRS) * N_MENT + pairs[2 * p];
    atomicAdd(&g_hist[key], 1);
}

__global__ __launch_bounds__(1024)
void sort_scan()
{
    __shared__ int part[1024];
    const int t = threadIdx.x;
    int v[4]; int s = 0;
#pragma unroll
    for (int j = 0; j < 4; j++) {
        int idx = t * 4 + j;
        v[j] = (idx < M_TOTAL) ? g_hist[idx] : 0;
        s += v[j];
    }
    part[t] = s;
    __syncthreads();
    for (int off = 1; off < 1024; off <<= 1) {
        int x = (t >= off) ? part[t - off] : 0;
        __syncthreads();
        part[t] += x;
        __syncthreads();
    }
    int run = (t == 0) ? 0 : part[t - 1];
#pragma unroll
    for (int j = 0; j < 4; j++) {
        int idx = t * 4 + j;
        if (idx < M_TOTAL) g_hist[idx] = run;   // exclusive offsets become cursors
        run += v[j];
    }
}

__global__ __launch_bounds__(256)
void sort_scatter(const int* __restrict__ pairs, const int* __restrict__ eds)
{
    int p = blockIdx.x * 256 + threadIdx.x;
    if (p >= P_TOTAL) return;
    const int b  = p / N_PAIRS;
    const int i1 = pairs[2 * p];
    const int i2 = pairs[2 * p + 1];
    const int key = b * N_MENT + i1;
    int pos = atomicAdd(&g_hist[key], 1);
    g_sorted[pos] = make_int4(key, b * N_MENT + i2, eds[p], p);
}

// ---------------------------------------------------------------------------
// fp16 GEMM (frozen from R13): 128x128 tile, warp 64x32, BK=32, 2-stage,
// ldmatrix.x4 + m16n8k16, __launch_bounds__(256,2) -> 2 CTAs/SM.
// ---------------------------------------------------------------------------
#define ASTR   40
#define STH    (128 * ASTR)
#define NITER  (HIDDEN / 32)

__global__ __launch_bounds__(256, 2)
void gemm_tc_kernel()
{
    __shared__ __align__(16) __half Asm[2][STH];
    __shared__ __align__(16) __half Bsm[2][STH];

    const int tid  = threadIdx.x;
    const int wid  = tid >> 5;
    const int lane = tid & 31;
    const int gid  = lane >> 2;
    const int tig  = lane & 3;

    const int nbase = blockIdx.x * 128;
    const int mbase = blockIdx.y * 128;
    const int wm = (wid >> 2) * 64;
    const int wn = (wid & 3) * 32;

    const __half* a_src[2]; const __half* b_src[2];
    uint32_t a_dst[2], b_dst[2], a_by[2];
#pragma unroll
    for (int i = 0; i < 2; i++) {
        const int ch = tid + i * 256;
        const int r = ch >> 2, c = ch & 3;
        a_by[i]  = (mbase + r < M_TOTAL) ? 16u : 0u;
        a_src[i] = g_Ah + (size_t)(mbase + r) * HIDDEN + c * 8;
        b_src[i] = g_Bh + (size_t)(nbase + r) * HIDDEN + c * 8;
        a_dst[i] = smem_u32(&Asm[0][r * ASTR + c * 8]);
        b_dst[i] = smem_u32(&Bsm[0][r * ASTR + c * 8]);
    }

    uint32_t a_off[4];
#pragma unroll
    for (int mt = 0; mt < 4; mt++)
        a_off[mt] = ((wm + mt * 16 + (lane & 15)) * ASTR + 8 * (lane >> 4)) * 2;
    uint32_t b_off[4];
#pragma unroll
    for (int nt = 0; nt < 4; nt++)
        b_off[nt] = ((wn + nt * 8 + (lane & 7)) * ASTR + 8 * (lane >> 3)) * 2;

    const uint32_t a_base = smem_u32(&Asm[0][0]);
    const uint32_t b_base = smem_u32(&Bsm[0][0]);
    const uint32_t stage_bytes = STH * 2;

    float acc[4][4][4];
#pragma unroll
    for (int mt = 0; mt < 4; mt++)
#pragma unroll
        for (int nt = 0; nt < 4; nt++)
#pragma unroll
            for (int r = 0; r < 4; r++) acc[mt][nt][r] = 0.f;

    auto load_stage = [&](int s) {
        const uint32_t bofs = (uint32_t)(s & 1) * stage_bytes;
        const int k0 = s * 32;
#pragma unroll
        for (int i = 0; i < 2; i++) {
            cp_async16(a_dst[i] + bofs, a_src[i] + k0, a_by[i]);
            cp_async16(b_dst[i] + bofs, b_src[i] + k0, 16u);
        }
        asm volatile("cp.async.commit_group;" ::: "memory");
    };

    load_stage(0);

    for (int kc = 0; kc < NITER; kc++) {
        if (kc + 1 < NITER) {
            load_stage(kc + 1);
            asm volatile("cp.async.wait_group 1;" ::: "memory");
        } else {
            asm volatile("cp.async.wait_group 0;" ::: "memory");
        }
        __syncthreads();

        const uint32_t abase = a_base + (kc & 1) * stage_bytes;
        const uint32_t bbase = b_base + (kc & 1) * stage_bytes;

        uint32_t bf[4][4];
#pragma unroll
        for (int nt = 0; nt < 4; nt++)
            ldsm_x4(bf[nt][0], bf[nt][1], bf[nt][2], bf[nt][3], bbase + b_off[nt]);

#pragma unroll
        for (int ks = 0; ks < 2; ks++) {
            uint32_t af[4][4];
#pragma unroll
            for (int mt = 0; mt < 4; mt++)
                ldsm_x4(af[mt][0], af[mt][1], af[mt][2], af[mt][3],
                        abase + a_off[mt] + ks * 32);
#pragma unroll
            for (int mt = 0; mt < 4; mt++)
#pragma unroll
                for (int nt = 0; nt < 4; nt++)
                    mma_f16(acc[mt][nt], af[mt], &bf[nt][ks * 2]);
        }
        __syncthreads();
    }

#pragma unroll
    for (int mt = 0; mt < 4; mt++) {
        const int m0 = mbase + wm + mt * 16 + gid;
#pragma unroll
        for (int nt = 0; nt < 4; nt++) {
            const int n0 = nbase + wn + nt * 8 + 2 * tig;
            if (m0 < M_TOTAL)
                *(__half2*)(g_ACh + (size_t)m0 * N_TOTAL + n0)
                    = __floats2half2_rn(acc[mt][nt][0], acc[mt][nt][1]);
            if (m0 + 8 < M_TOTAL)
                *(__half2*)(g_ACh + (size_t)(m0 + 8) * N_TOTAL + n0)
                    = __floats2half2_rn(acc[mt][nt][2], acc[mt][nt][3]);
        }
    }
}

// ---------------------------------------------------------------------------
// ed kernel (j-tiled, smem cached)
// ---------------------------------------------------------------------------
#define ED_JTILE 32

__global__ __launch_bounds__(128)
void ed_kernel(const float* __restrict__ ed_table,
               const float* __restrict__ W1,
               const float* __restrict__ b1)
{
    __shared__ float s_ed[ED_COUNT * META];
    __shared__ float s_w[META * ED_JTILE];
    const int tid = threadIdx.x;
    const int jbase = blockIdx.x * ED_JTILE;

    for (int i = tid; i < ED_COUNT * META; i += 128) s_ed[i] = ed_table[i];
    for (int i = tid; i < META * ED_JTILE; i += 128) {
        const int t = i / ED_JTILE, j = i % ED_JTILE;
        s_w[i] = W1[(size_t)(2 * HIDDEN + t) * HIDDEN + jbase + j];
    }
    __syncthreads();

    const int jcol = tid & 31;
    const int erow0 = tid >> 5;
    const float bias = b1[jbase + jcol];
    for (int e = erow0; e < ED_COUNT; e += 4) {
        float s = bias;
        const float* ed = s_ed + e * META;
#pragma unroll
        for (int t = 0; t < META; t++)
            s = fmaf(ed[t], s_w[t * ED_JTILE + jcol], s);
        g_Eh[(size_t)e * HIDDEN + jbase + jcol] = __float2half_rn(s);
    }
}

// ---------------------------------------------------------------------------
// pair kernel on SORTED pairs: warp owns 16 consecutive pairs; A row cached
// in registers across same-i1 runs; W2 preloaded to registers.
// ---------------------------------------------------------------------------
#define PAIRS_PER_WARP 16
#define PAIRS_PER_BLOCK (8 * PAIRS_PER_WARP)     // 128

__global__ __launch_bounds__(256)
void pair_kernel(const float* __restrict__ W2,
                 const float* __restrict__ b2,
                 float*       __restrict__ out)
{
    const int wglob = blockIdx.x * 8 + (threadIdx.x >> 5);
    const int lane  = threadIdx.x & 31;
    const int base  = wglob * PAIRS_PER_WARP;
    if (base >= P_TOTAL) return;

    // per-warp constants in registers
    const float4* Wrow = (const float4*)W2;
    float4 w2f[6];
#pragma unroll
    for (int i = 0; i < 3; i++) {
        const int idx = lane + i * 32;
        w2f[2 * i]     = Wrow[2 * idx];
        w2f[2 * i + 1] = Wrow[2 * idx + 1];
    }
    const float b2v = b2[0];

    int cached_i1 = -1;
    uint4 a[3];

#pragma unroll 1
    for (int t = 0; t < PAIRS_PER_WARP; t++) {
        const int4 rec = g_sorted[base + t];     // {i1g, i2g, ed, p}
        if (rec.x != cached_i1) {
            const uint4* Arow = (const uint4*)(g_ACh + (size_t)rec.x * N_TOTAL);
#pragma unroll
            for (int i = 0; i < 3; i++) a[i] = Arow[lane + i * 32];
            cached_i1 = rec.x;
        }
        const uint4* Crow = (const uint4*)(g_ACh + (size_t)rec.y * N_TOTAL + HIDDEN);
        const uint4* Erow = (const uint4*)(g_Eh  + (size_t)rec.z * HIDDEN);

        float acc = 0.f;
#pragma unroll
        for (int i = 0; i < 3; i++) {
            const int idx = lane + i * 32;
            uint4 c = Crow[idx];
            uint4 e = Erow[idx];
            const float4 w0 = w2f[2 * i];
            const float4 w1 = w2f[2 * i + 1];
            float2 fa, fc, fe;
            float h;
            fa = h2f(a[i].x); fc = h2f(c.x); fe = h2f(e.x);
            h = fa.x + fc.x + fe.x; if (h > 0.f) acc = fmaf(h, w0.x, acc);
            h = fa.y + fc.y + fe.y; if (h > 0.f) acc = fmaf(h, w0.y, acc);
            fa = h2f(a[i].y); fc = h2f(c.y); fe = h2f(e.y);
            h = fa.x + fc.x + fe.x; if (h > 0.f) acc = fmaf(h, w0.z, acc);
            h = fa.y + fc.y + fe.y; if (h > 0.f) acc = fmaf(h, w0.w, acc);
            fa = h2f(a[i].z); fc = h2f(c.z); fe = h2f(e.z);
            h = fa.x + fc.x + fe.x; if (h > 0.f) acc = fmaf(h, w1.x, acc);
            h = fa.y + fc.y + fe.y; if (h > 0.f) acc = fmaf(h, w1.y, acc);
            fa = h2f(a[i].w); fc = h2f(c.w); fe = h2f(e.w);
            h = fa.x + fc.x + fe.x; if (h > 0.f) acc = fmaf(h, w1.z, acc);
            h = fa.y + fc.y + fe.y; if (h > 0.f) acc = fmaf(h, w1.w, acc);
        }
#pragma unroll
        for (int off = 16; off; off >>= 1)
            acc += __shfl_xor_sync(0xffffffffu, acc, off);
        if (lane == 0) out[rec.w] = acc + b2v;
    }
}

// ---------------------------------------------------------------------------
// Launch
// ---------------------------------------------------------------------------
extern "C" void kernel_launch(void* const* d_in, const int* in_sizes, int n_in,
                              void* d_out, int out_size)
{
    const float* mention  = (const float*)d_in[0];
    const int*   pairs    = (const int*)  d_in[1];
    const int*   eds      = (const int*)  d_in[2];
    const float* ed_table = (const float*)d_in[3];
    const float* W1       = (const float*)d_in[4];
    const float* b1       = (const float*)d_in[5];
    const float* W2       = (const float*)d_in[6];
    const float* b2       = (const float*)d_in[7];
    float* out = (float*)d_out;
    (void)in_sizes; (void)n_in; (void)out_size;

    prep_a<<<(M_TOTAL * HIDDEN / 4 + 255) / 256, 256>>>(mention);  // + hist zero
    {
        dim3 g(HIDDEN / 32, N_TOTAL / 32);
        dim3 t(32, 8);
        prep_b<<<g, t>>>(W1);
    }
    sort_count<<<(P_TOTAL + 255) / 256, 256>>>(pairs);
    sort_scan<<<1, 1024>>>();
    sort_scatter<<<(P_TOTAL + 255) / 256, 256>>>(pairs, eds);
    ed_kernel<<<HIDDEN / ED_JTILE, 128>>>(ed_table, W1, b1);
    {
        dim3 g(N_TOTAL / 128, (M_TOTAL + 127) / 128);
        gemm_tc_kernel<<<g, 256>>>();
    }
    pair_kernel<<<P_TOTAL / PAIRS_PER_BLOCK, 256>>>(W2, b2, out);
}

// round 16
// speedup vs baseline: 1.1859x; 1.1859x over previous
#include <cuda_runtime.h>
#include <cuda_fp16.h>
#include <cstdint>
#include <cstddef>

// ---------------------------------------------------------------------------
// Problem constants
// ---------------------------------------------------------------------------
#define HIDDEN   768
#define META     25
#define ED_COUNT 300
#define BATCH    2
#define N_MENT   2000
#define N_PAIRS  40000
#define M_TOTAL  (BATCH * N_MENT)        // 4000
#define N_TOTAL  (2 * HIDDEN)            // 1536
#define P_TOTAL  (BATCH * N_PAIRS)       // 80000

// ---------------------------------------------------------------------------
// Device scratch
// ---------------------------------------------------------------------------
__device__ __half g_ACh[(size_t)M_TOTAL * N_TOTAL];   // 12.3 MB  (A|C rows, fp16)
__device__ __half g_Eh[(size_t)ED_COUNT * HIDDEN];    // 0.46 MB
__device__ __half g_Ah[(size_t)M_TOTAL * HIDDEN];     // 6.1 MB  mentions fp16
__device__ __half g_Bh[(size_t)N_TOTAL * HIDDEN];     // 2.4 MB  W1^T fp16 [n][k]

// ---------------------------------------------------------------------------
// helpers
// ---------------------------------------------------------------------------
__device__ __forceinline__ uint32_t smem_u32(const void* p) {
    uint32_t a;
    asm("{ .reg .u64 t; cvta.to.shared.u64 t, %1; cvt.u32.u64 %0, t; }" : "=r"(a) : "l"(p));
    return a;
}
__device__ __forceinline__ void cp_async16(uint32_t dst, const void* src, uint32_t src_bytes) {
    asm volatile("cp.async.ca.shared.global [%0], [%1], 16, %2;"
                 :: "r"(dst), "l"(src), "r"(src_bytes) : "memory");
}
__device__ __forceinline__ void ldsm_x4(uint32_t& r0, uint32_t& r1, uint32_t& r2,
                                        uint32_t& r3, uint32_t addr) {
    asm volatile("ldmatrix.sync.aligned.m8n8.x4.shared.b16 {%0,%1,%2,%3}, [%4];"
                 : "=r"(r0), "=r"(r1), "=r"(r2), "=r"(r3) : "r"(addr));
}
__device__ __forceinline__ void mma_f16(float* c, const uint32_t* a, const uint32_t* b) {
    asm volatile(
        "mma.sync.aligned.m16n8k16.row.col.f32.f16.f16.f32 "
        "{%0,%1,%2,%3}, {%4,%5,%6,%7}, {%8,%9}, {%0,%1,%2,%3};"
        : "+f"(c[0]), "+f"(c[1]), "+f"(c[2]), "+f"(c[3])
        : "r"(a[0]), "r"(a[1]), "r"(a[2]), "r"(a[3]), "r"(b[0]), "r"(b[1]));
}
__device__ __forceinline__ float2 h2f(uint32_t u) {
    __half2 h = *reinterpret_cast<__half2*>(&u);
    return __half22float2(h);
}

// ---------------------------------------------------------------------------
// Fused prep kernel: [0,3000) prep_a | [3000,4152) prep_b | [4152,4176) ed
// One launch instead of three; independent stages fill the chip concurrently.
// ---------------------------------------------------------------------------
#define ED_JTILE   32
#define PA_BLOCKS  (M_TOTAL * HIDDEN / 4 / 256)          // 3000
#define PB_BLOCKS  (24 * 48)                             // 1152
#define ED_BLOCKS  (HIDDEN / ED_JTILE)                   // 24
#define PREP_GRID  (PA_BLOCKS + PB_BLOCKS + ED_BLOCKS)   // 4176

__global__ __launch_bounds__(256)
void prep_all(const float* __restrict__ A,
              const float* __restrict__ W1,
              const float* __restrict__ ed_table,
              const float* __restrict__ b1)
{
    __shared__ float sbuf[ED_COUNT * META + META * ED_JTILE];   // 33.2 KB
    const int blk = blockIdx.x;
    const int tid = threadIdx.x;

    if (blk < PA_BLOCKS) {
        // ---- mentions fp32 -> fp16 ----
        const int i = blk * 256 + tid;                   // one float4 per thread
        float4 v = ((const float4*)A)[i];
        __half2* dst = (__half2*)(g_Ah + (size_t)i * 4);
        dst[0] = __floats2half2_rn(v.x, v.y);
        dst[1] = __floats2half2_rn(v.z, v.w);
    } else if (blk < PA_BLOCKS + PB_BLOCKS) {
        // ---- W1 transpose -> g_Bh[n][k] fp16 ----
        const int bid = blk - PA_BLOCKS;
        const int kt = bid % 24;                         // k tile within half
        const int nt = bid / 24;                         // global n tile (0..47)
        float (*t)[33] = (float(*)[33])sbuf;
        const int c = tid & 31, ty = tid >> 5;           // 32 x 8
        const int half = (nt * 32) >= HIDDEN;
        const int nloc = nt * 32 - half * HIDDEN;
        for (int r = ty; r < 32; r += 8)
            t[r][c] = W1[(size_t)(half * HIDDEN + kt * 32 + r) * HIDDEN + nloc + c];
        __syncthreads();
        for (int rr = ty; rr < 32; rr += 8)
            g_Bh[(size_t)(nt * 32 + rr) * HIDDEN + kt * 32 + c]
                = __float2half_rn(t[c][rr]);
    } else {
        // ---- E[e][j] = b1[j] + ed_table[e]·W1_tail[:,j] -> fp16 ----
        const int jbase = (blk - PA_BLOCKS - PB_BLOCKS) * ED_JTILE;
        float* s_ed = sbuf;
        float* s_w  = sbuf + ED_COUNT * META;
        for (int i = tid; i < ED_COUNT * META; i += 256) s_ed[i] = ed_table[i];
        for (int i = tid; i < META * ED_JTILE; i += 256) {
            const int t_ = i / ED_JTILE, j = i % ED_JTILE;
            s_w[i] = W1[(size_t)(2 * HIDDEN + t_) * HIDDEN + jbase + j];
        }
        __syncthreads();
        const int jcol = tid & 31;
        const int erow0 = tid >> 5;                      // 0..7
        const float bias = b1[jbase + jcol];
        for (int e = erow0; e < ED_COUNT; e += 8) {
            float s = bias;
            const float* ed = s_ed + e * META;
#pragma unroll
            for (int t_ = 0; t_ < META; t_++)
                s = fmaf(ed[t_], s_w[t_ * ED_JTILE + jcol], s);
            g_Eh[(size_t)e * HIDDEN + jbase + jcol] = __float2half_rn(s);
        }
    }
}

// ---------------------------------------------------------------------------
// fp16 GEMM (frozen from R13): 128x128 tile, warp 64x32, BK=32, 2-stage,
// ldmatrix.x4 + m16n8k16, __launch_bounds__(256,2) -> 2 CTAs/SM.
// ---------------------------------------------------------------------------
#define ASTR   40
#define STH    (128 * ASTR)
#define NITER  (HIDDEN / 32)

__global__ __launch_bounds__(256, 2)
void gemm_tc_kernel()
{
    __shared__ __align__(16) __half Asm[2][STH];
    __shared__ __align__(16) __half Bsm[2][STH];

    const int tid  = threadIdx.x;
    const int wid  = tid >> 5;
    const int lane = tid & 31;
    const int gid  = lane >> 2;
    const int tig  = lane & 3;

    const int nbase = blockIdx.x * 128;
    const int mbase = blockIdx.y * 128;
    const int wm = (wid >> 2) * 64;
    const int wn = (wid & 3) * 32;

    const __half* a_src[2]; const __half* b_src[2];
    uint32_t a_dst[2], b_dst[2], a_by[2];
#pragma unroll
    for (int i = 0; i < 2; i++) {
        const int ch = tid + i * 256;
        const int r = ch >> 2, c = ch & 3;
        a_by[i]  = (mbase + r < M_TOTAL) ? 16u : 0u;
        a_src[i] = g_Ah + (size_t)(mbase + r) * HIDDEN + c * 8;
        b_src[i] = g_Bh + (size_t)(nbase + r) * HIDDEN + c * 8;
        a_dst[i] = smem_u32(&Asm[0][r * ASTR + c * 8]);
        b_dst[i] = smem_u32(&Bsm[0][r * ASTR + c * 8]);
    }

    uint32_t a_off[4];
#pragma unroll
    for (int mt = 0; mt < 4; mt++)
        a_off[mt] = ((wm + mt * 16 + (lane & 15)) * ASTR + 8 * (lane >> 4)) * 2;
    uint32_t b_off[4];
#pragma unroll
    for (int nt = 0; nt < 4; nt++)
        b_off[nt] = ((wn + nt * 8 + (lane & 7)) * ASTR + 8 * (lane >> 3)) * 2;

    const uint32_t a_base = smem_u32(&Asm[0][0]);
    const uint32_t b_base = smem_u32(&Bsm[0][0]);
    const uint32_t stage_bytes = STH * 2;

    float acc[4][4][4];
#pragma unroll
    for (int mt = 0; mt < 4; mt++)
#pragma unroll
        for (int nt = 0; nt < 4; nt++)
#pragma unroll
            for (int r = 0; r < 4; r++) acc[mt][nt][r] = 0.f;

    auto load_stage = [&](int s) {
        const uint32_t bofs = (uint32_t)(s & 1) * stage_bytes;
        const int k0 = s * 32;
#pragma unroll
        for (int i = 0; i < 2; i++) {
            cp_async16(a_dst[i] + bofs, a_src[i] + k0, a_by[i]);
            cp_async16(b_dst[i] + bofs, b_src[i] + k0, 16u);
        }
        asm volatile("cp.async.commit_group;" ::: "memory");
    };

    load_stage(0);

    for (int kc = 0; kc < NITER; kc++) {
        if (kc + 1 < NITER) {
            load_stage(kc + 1);
            asm volatile("cp.async.wait_group 1;" ::: "memory");
        } else {
            asm volatile("cp.async.wait_group 0;" ::: "memory");
        }
        __syncthreads();

        const uint32_t abase = a_base + (kc & 1) * stage_bytes;
        const uint32_t bbase = b_base + (kc & 1) * stage_bytes;

        uint32_t bf[4][4];
#pragma unroll
        for (int nt = 0; nt < 4; nt++)
            ldsm_x4(bf[nt][0], bf[nt][1], bf[nt][2], bf[nt][3], bbase + b_off[nt]);

#pragma unroll
        for (int ks = 0; ks < 2; ks++) {
            uint32_t af[4][4];
#pragma unroll
            for (int mt = 0; mt < 4; mt++)
                ldsm_x4(af[mt][0], af[mt][1], af[mt][2], af[mt][3],
                        abase + a_off[mt] + ks * 32);
#pragma unroll
            for (int mt = 0; mt < 4; mt++)
#pragma unroll
                for (int nt = 0; nt < 4; nt++)
                    mma_f16(acc[mt][nt], af[mt], &bf[nt][ks * 2]);
        }
        __syncthreads();
    }

#pragma unroll
    for (int mt = 0; mt < 4; mt++) {
        const int m0 = mbase + wm + mt * 16 + gid;
#pragma unroll
        for (int nt = 0; nt < 4; nt++) {
            const int n0 = nbase + wn + nt * 8 + 2 * tig;
            if (m0 < M_TOTAL)
                *(__half2*)(g_ACh + (size_t)m0 * N_TOTAL + n0)
                    = __floats2half2_rn(acc[mt][nt][0], acc[mt][nt][1]);
            if (m0 + 8 < M_TOTAL)
                *(__half2*)(g_ACh + (size_t)(m0 + 8) * N_TOTAL + n0)
                    = __floats2half2_rn(acc[mt][nt][2], acc[mt][nt][3]);
        }
    }
}

// ---------------------------------------------------------------------------
// pair kernel (frozen from R13): warp/pair, fp16 rows, fp32 math
// ---------------------------------------------------------------------------
__global__ __launch_bounds__(256)
void pair_kernel(const int*   __restrict__ pairs,
                 const int*   __restrict__ eds,
                 const float* __restrict__ W2,
                 const float* __restrict__ b2,
                 float*       __restrict__ out)
{
    const int p = blockIdx.x * 8 + (threadIdx.x >> 5);
    if (p >= P_TOTAL) return;
    const int lane = threadIdx.x & 31;

    const int b  = p / N_PAIRS;
    const int i1 = pairs[2 * p];
    const int i2 = pairs[2 * p + 1];
    const int ed = eds[p];

    const uint4* Arow = (const uint4*)(g_ACh + (size_t)(b * N_MENT + i1) * N_TOTAL);
    const uint4* Crow = (const uint4*)(g_ACh + (size_t)(b * N_MENT + i2) * N_TOTAL + HIDDEN);
    const uint4* Erow = (const uint4*)(g_Eh  + (size_t)ed * HIDDEN);
    const float4* Wrow = (const float4*)W2;

    float acc = 0.f;
#pragma unroll
    for (int i = 0; i < HIDDEN / 8 / 32; i++) {
        const int idx = lane + i * 32;
        uint4 a = Arow[idx];
        uint4 c = Crow[idx];
        uint4 e = Erow[idx];
        float4 w0 = Wrow[2 * idx];
        float4 w1 = Wrow[2 * idx + 1];
        float2 fa, fc, fe;
        float h;
        fa = h2f(a.x); fc = h2f(c.x); fe = h2f(e.x);
        h = fa.x + fc.x + fe.x; if (h > 0.f) acc = fmaf(h, w0.x, acc);
        h = fa.y + fc.y + fe.y; if (h > 0.f) acc = fmaf(h, w0.y, acc);
        fa = h2f(a.y); fc = h2f(c.y); fe = h2f(e.y);
        h = fa.x + fc.x + fe.x; if (h > 0.f) acc = fmaf(h, w0.z, acc);
        h = fa.y + fc.y + fe.y; if (h > 0.f) acc = fmaf(h, w0.w, acc);
        fa = h2f(a.z); fc = h2f(c.z); fe = h2f(e.z);
        h = fa.x + fc.x + fe.x; if (h > 0.f) acc = fmaf(h, w1.x, acc);
        h = fa.y + fc.y + fe.y; if (h > 0.f) acc = fmaf(h, w1.y, acc);
        fa = h2f(a.w); fc = h2f(c.w); fe = h2f(e.w);
        h = fa.x + fc.x + fe.x; if (h > 0.f) acc = fmaf(h, w1.z, acc);
        h = fa.y + fc.y + fe.y; if (h > 0.f) acc = fmaf(h, w1.w, acc);
    }
#pragma unroll
    for (int off = 16; off; off >>= 1)
        acc += __shfl_xor_sync(0xffffffffu, acc, off);
    if (lane == 0) out[p] = acc + b2[0];
}

// ---------------------------------------------------------------------------
// Launch: 3 kernels total (was 5)
// ---------------------------------------------------------------------------
extern "C" void kernel_launch(void* const* d_in, const int* in_sizes, int n_in,
                              void* d_out, int out_size)
{
    const float* mention  = (const float*)d_in[0];
    const int*   pairs    = (const int*)  d_in[1];
    const int*   eds      = (const int*)  d_in[2];
    const float* ed_table = (const float*)d_in[3];
    const float* W1       = (const float*)d_in[4];
    const float* b1       = (const float*)d_in[5];
    const float* W2       = (const float*)d_in[6];
    const float* b2       = (const float*)d_in[7];
    float* out = (float*)d_out;
    (void)in_sizes; (void)n_in; (void)out_size;

    prep_all<<<PREP_GRID, 256>>>(mention, W1, ed_table, b1);
    {
        dim3 g(N_TOTAL / 128, (M_TOTAL + 127) / 128);   // (12, 32)
        gemm_tc_kernel<<<g, 256>>>();
    }
    pair_kernel<<<(P_TOTAL + 7) / 8, 256>>>(pairs, eds, W2, b2, out);
}